// round 1
// baseline (speedup 1.0000x reference)
#include <cuda_runtime.h>
#include <cstdint>

// Problem constants
#define NN 100000
#define EE 1600000
#define NFEAT 256
#define NHID 128
#define LATENT 64

// Scratch buffers (allocation-free rule: __device__ globals)
__device__ float g_bufA[(size_t)NN * NHID];
__device__ float g_bufB[(size_t)NN * NHID];

// ---------------------------------------------------------------------------
// Tiled SGEMM: C[M,Nc] = A[M,K] @ B[K,Nc] (+ bias), row-major.
// BM=128, BN=128, BK=16, 256 threads, 8x8 per-thread micro-tile.
// ---------------------------------------------------------------------------
template <int BM, int BN, int BK, int TM, int TN>
__global__ __launch_bounds__(256) void sgemm_kernel(
    const float* __restrict__ A, const float* __restrict__ B,
    const float* __restrict__ bias, float* __restrict__ C,
    int M, int Nc, int K)
{
    __shared__ float As[BK][BM];
    __shared__ float Bs[BK][BN];

    const int tid  = threadIdx.x;            // 0..255
    const int tcol = tid % (BN / TN);         // 0..15
    const int trow = tid / (BN / TN);         // 0..15
    const int blockRow = blockIdx.y * BM;
    const int blockCol = blockIdx.x * BN;

    float acc[TM][TN];
#pragma unroll
    for (int i = 0; i < TM; i++)
#pragma unroll
        for (int j = 0; j < TN; j++) acc[i][j] = 0.f;

    // A tile loader: BM*BK floats, float4 per thread per pass
    const int aRow0 = tid / (BK / 4);          // 0..63
    const int aCol4 = (tid % (BK / 4)) * 4;    // 0,4,8,12
    // B tile loader
    const int bRow0 = tid / (BN / 4);          // 0..7
    const int bCol4 = (tid % (BN / 4)) * 4;    // 0..124

    for (int k0 = 0; k0 < K; k0 += BK) {
#pragma unroll
        for (int i = 0; i < BM; i += 256 / (BK / 4)) {   // step 64
            int r = aRow0 + i;
            int grow = blockRow + r;
            float4 v = make_float4(0.f, 0.f, 0.f, 0.f);
            if (grow < M)
                v = *reinterpret_cast<const float4*>(A + (size_t)grow * K + k0 + aCol4);
            As[aCol4 + 0][r] = v.x;
            As[aCol4 + 1][r] = v.y;
            As[aCol4 + 2][r] = v.z;
            As[aCol4 + 3][r] = v.w;
        }
#pragma unroll
        for (int i = 0; i < BK; i += 256 / (BN / 4)) {   // step 8
            int r = bRow0 + i;
            int gcol = blockCol + bCol4;
            float4 v = make_float4(0.f, 0.f, 0.f, 0.f);
            if (gcol < Nc)
                v = *reinterpret_cast<const float4*>(B + (size_t)(k0 + r) * Nc + gcol);
            *reinterpret_cast<float4*>(&Bs[r][bCol4]) = v;
        }
        __syncthreads();

#pragma unroll
        for (int k = 0; k < BK; k++) {
            float ra[TM], rb[TN];
            *reinterpret_cast<float4*>(&ra[0]) =
                *reinterpret_cast<const float4*>(&As[k][trow * TM + 0]);
            *reinterpret_cast<float4*>(&ra[4]) =
                *reinterpret_cast<const float4*>(&As[k][trow * TM + 4]);
            *reinterpret_cast<float4*>(&rb[0]) =
                *reinterpret_cast<const float4*>(&Bs[k][tcol * TN + 0]);
            *reinterpret_cast<float4*>(&rb[4]) =
                *reinterpret_cast<const float4*>(&Bs[k][tcol * TN + 4]);
#pragma unroll
            for (int i = 0; i < TM; i++)
#pragma unroll
                for (int j = 0; j < TN; j++)
                    acc[i][j] = fmaf(ra[i], rb[j], acc[i][j]);
        }
        __syncthreads();
    }

    // Epilogue (+bias); Nc is always a multiple of 4
#pragma unroll
    for (int i = 0; i < TM; i++) {
        int grow = blockRow + trow * TM + i;
        if (grow >= M) continue;
#pragma unroll
        for (int j = 0; j < TN; j += 4) {
            int gcol = blockCol + tcol * TN + j;
            if (gcol < Nc) {
                float4 v;
                v.x = acc[i][j + 0] + (bias ? bias[gcol + 0] : 0.f);
                v.y = acc[i][j + 1] + (bias ? bias[gcol + 1] : 0.f);
                v.z = acc[i][j + 2] + (bias ? bias[gcol + 2] : 0.f);
                v.w = acc[i][j + 3] + (bias ? bias[gcol + 3] : 0.f);
                *reinterpret_cast<float4*>(C + (size_t)grow * Nc + gcol) = v;
            }
        }
    }
}

// ---------------------------------------------------------------------------
// SpMM scatter: one warp per edge. out[row] += w * support[col]  (128 floats).
// Each lane handles one float4 and issues a 128-bit vector reduction.
// ---------------------------------------------------------------------------
__global__ __launch_bounds__(256) void spmm_scatter(
    const int* __restrict__ ei,      // [2, E] row-major: rows at ei[0..E), cols at ei[E..2E)
    const float* __restrict__ ew,    // [E]
    const float* __restrict__ support,  // [N, 128]
    float* __restrict__ out,            // [N, 128] (pre-zeroed)
    int E)
{
    int warp = (blockIdx.x * blockDim.x + threadIdx.x) >> 5;
    int lane = threadIdx.x & 31;
    if (warp >= E) return;

    int row = __ldg(ei + warp);
    int col = __ldg(ei + E + warp);
    float w = __ldg(ew + warp);

    float4 v = *reinterpret_cast<const float4*>(support + (size_t)col * NHID + lane * 4);
    v.x *= w; v.y *= w; v.z *= w; v.w *= w;

    float* dst = out + (size_t)row * NHID + lane * 4;
    asm volatile("red.global.add.v4.f32 [%0], {%1, %2, %3, %4};"
                 :: "l"(dst), "f"(v.x), "f"(v.y), "f"(v.z), "f"(v.w)
                 : "memory");
}

// ---------------------------------------------------------------------------
// out[i] = relu(in[i] + bias[i % 128]), vectorized by float4
// ---------------------------------------------------------------------------
__global__ __launch_bounds__(256) void bias_relu(
    const float* __restrict__ in, const float* __restrict__ bias,
    float* __restrict__ out, int total)
{
    int i = blockIdx.x * blockDim.x + threadIdx.x;   // float4 index
    if (i * 4 >= total) return;
    float4 v = reinterpret_cast<const float4*>(in)[i];
    int col = (i * 4) & (NHID - 1);
    v.x = fmaxf(v.x + bias[col + 0], 0.f);
    v.y = fmaxf(v.y + bias[col + 1], 0.f);
    v.z = fmaxf(v.z + bias[col + 2], 0.f);
    v.w = fmaxf(v.w + bias[col + 3], 0.f);
    reinterpret_cast<float4*>(out)[i] = v;
}

extern "C" void kernel_launch(void* const* d_in, const int* in_sizes, int n_in,
                              void* d_out, int out_size)
{
    const float* x      = (const float*)d_in[0];
    const int*   ei     = (const int*)  d_in[1];
    const float* ew     = (const float*)d_in[2];
    const float* gc1_w  = (const float*)d_in[3];
    const float* gc1_b  = (const float*)d_in[4];
    const float* gc2_w  = (const float*)d_in[5];
    const float* gc2_b  = (const float*)d_in[6];
    const float* mu_w   = (const float*)d_in[7];
    const float* mu_b   = (const float*)d_in[8];
    const float* lv_w   = (const float*)d_in[9];
    const float* lv_b   = (const float*)d_in[10];
    float* out = (float*)d_out;

    float *A, *B;
    cudaGetSymbolAddress((void**)&A, g_bufA);
    cudaGetSymbolAddress((void**)&B, g_bufB);

    const size_t hidBytes = (size_t)NN * NHID * sizeof(float);
    const dim3 gGemm128(1, (NN + 127) / 128);
    const int scatterBlocks = (int)(((long long)EE * 32 + 255) / 256);
    const int brBlocks = (NN * NHID / 4 + 255) / 256;

    // Layer 1: support1 = x @ gc1_w ; acc = spmm(support1) ; h1 = relu(acc + b1)
    sgemm_kernel<128, 128, 16, 8, 8><<<gGemm128, 256>>>(x, gc1_w, nullptr, A, NN, NHID, NFEAT);
    cudaMemsetAsync(B, 0, hidBytes);
    spmm_scatter<<<scatterBlocks, 256>>>(ei, ew, A, B, EE);
    bias_relu<<<brBlocks, 256>>>(B, gc1_b, A, NN * NHID);     // A = h1

    // Layer 2
    sgemm_kernel<128, 128, 16, 8, 8><<<gGemm128, 256>>>(A, gc2_w, nullptr, B, NN, NHID, NHID);
    cudaMemsetAsync(A, 0, hidBytes);
    spmm_scatter<<<scatterBlocks, 256>>>(ei, ew, B, A, EE);
    bias_relu<<<brBlocks, 256>>>(A, gc2_b, B, NN * NHID);     // B = h2

    // Heads: mu = h2 @ mu_w + mu_b ; log_var = h2 @ lv_w + lv_b
    sgemm_kernel<128, 128, 16, 8, 8><<<gGemm128, 256>>>(B, mu_w, mu_b, out, NN, LATENT, NHID);
    sgemm_kernel<128, 128, 16, 8, 8><<<gGemm128, 256>>>(B, lv_w, lv_b, out + (size_t)NN * LATENT, NN, LATENT, NHID);
}

// round 3
// speedup vs baseline: 1.6768x; 1.6768x over previous
#include <cuda_runtime.h>
#include <cstdint>

// Problem constants
#define NN 100000
#define EE 1600000
#define NFEAT 256
#define NHID 128
#define LATENT 64
#define SCAN_CHUNK 2048
#define NTOT (NN + 1)
#define NSCANBLK ((NTOT + SCAN_CHUNK - 1) / SCAN_CHUNK)

// Scratch (allocation-free rule: __device__ globals)
__device__ float g_bufA[(size_t)NN * NHID];
__device__ float g_bufB[(size_t)NN * NHID];
__device__ int   g_cnt[NN];
__device__ int   g_rowptr[NTOT];
__device__ int   g_blocksums[NSCANBLK + 1];
__device__ int   g_colS[EE];
__device__ float g_wS[EE];
__device__ float g_wcat[NHID * NHID];
__device__ float g_bcat[NHID];

// ---------------------------------------------------------------------------
// CSR build: histogram -> exclusive scan -> scatter
// ---------------------------------------------------------------------------
__global__ __launch_bounds__(256) void hist_kernel(const int* __restrict__ ei)
{
    int e = blockIdx.x * blockDim.x + threadIdx.x;
    if (e < EE) atomicAdd(&g_cnt[ei[e]], 1);
}

__global__ __launch_bounds__(256) void scan1_kernel()
{
    __shared__ int sh[256];
    int b = blockIdx.x, t = threadIdx.x;
    int base = b * SCAN_CHUNK + t * 8;
    int v[8];
    int sum = 0;
#pragma unroll
    for (int k = 0; k < 8; k++) {
        int idx = base + k;
        int c = (idx < NN) ? g_cnt[idx] : 0;
        v[k] = sum;           // thread-local exclusive prefix
        sum += c;
    }
    sh[t] = sum;
    __syncthreads();
    for (int off = 1; off < 256; off <<= 1) {
        int x = (t >= off) ? sh[t - off] : 0;
        __syncthreads();
        sh[t] += x;
        __syncthreads();
    }
    int threadExcl = sh[t] - sum;   // exclusive prefix of thread totals
#pragma unroll
    for (int k = 0; k < 8; k++) {
        int idx = base + k;
        if (idx < NTOT) g_rowptr[idx] = threadExcl + v[k];
    }
    if (t == 255) g_blocksums[b] = sh[255];
}

__global__ void scan2_kernel()
{
    if (threadIdx.x == 0) {
        int s = 0;
        for (int i = 0; i < NSCANBLK; i++) {
            int c = g_blocksums[i];
            g_blocksums[i] = s;
            s += c;
        }
    }
}

__global__ __launch_bounds__(256) void scan3_kernel()
{
    int i = blockIdx.x * blockDim.x + threadIdx.x;
    if (i < NTOT) g_rowptr[i] += g_blocksums[i / SCAN_CHUNK];
}

__global__ __launch_bounds__(256) void scatter_kernel(
    const int* __restrict__ ei, const float* __restrict__ ew)
{
    int e = blockIdx.x * blockDim.x + threadIdx.x;
    if (e >= EE) return;
    int r = ei[e];
    int pos = g_rowptr[r] + atomicAdd(&g_cnt[r], 1);
    g_colS[pos] = ei[EE + e];
    g_wS[pos]   = ew[e];
}

// ---------------------------------------------------------------------------
// CSR SpMM fused with bias + ReLU: one warp per row, one float4 per lane.
// out[row, :] = relu( sum_e w[e] * support[col[e], :] + bias )
// ---------------------------------------------------------------------------
__global__ __launch_bounds__(256) void spmm_csr_bias_relu(
    const float* __restrict__ support, const float* __restrict__ bias,
    float* __restrict__ out)
{
    int warp = (blockIdx.x * blockDim.x + threadIdx.x) >> 5;
    if (warp >= NN) return;
    int lane = threadIdx.x & 31;

    int s = __ldg(&g_rowptr[warp]);
    int e = __ldg(&g_rowptr[warp + 1]);

    float4 acc = make_float4(0.f, 0.f, 0.f, 0.f);
    int i = s;
    for (; i + 4 <= e; i += 4) {
        int   c0 = __ldg(&g_colS[i]),     c1 = __ldg(&g_colS[i + 1]);
        int   c2 = __ldg(&g_colS[i + 2]), c3 = __ldg(&g_colS[i + 3]);
        float w0 = __ldg(&g_wS[i]),       w1 = __ldg(&g_wS[i + 1]);
        float w2 = __ldg(&g_wS[i + 2]),   w3 = __ldg(&g_wS[i + 3]);
        float4 v0 = __ldg(reinterpret_cast<const float4*>(support + (size_t)c0 * NHID) + lane);
        float4 v1 = __ldg(reinterpret_cast<const float4*>(support + (size_t)c1 * NHID) + lane);
        float4 v2 = __ldg(reinterpret_cast<const float4*>(support + (size_t)c2 * NHID) + lane);
        float4 v3 = __ldg(reinterpret_cast<const float4*>(support + (size_t)c3 * NHID) + lane);
        acc.x = fmaf(w0, v0.x, acc.x); acc.y = fmaf(w0, v0.y, acc.y);
        acc.z = fmaf(w0, v0.z, acc.z); acc.w = fmaf(w0, v0.w, acc.w);
        acc.x = fmaf(w1, v1.x, acc.x); acc.y = fmaf(w1, v1.y, acc.y);
        acc.z = fmaf(w1, v1.z, acc.z); acc.w = fmaf(w1, v1.w, acc.w);
        acc.x = fmaf(w2, v2.x, acc.x); acc.y = fmaf(w2, v2.y, acc.y);
        acc.z = fmaf(w2, v2.z, acc.z); acc.w = fmaf(w2, v2.w, acc.w);
        acc.x = fmaf(w3, v3.x, acc.x); acc.y = fmaf(w3, v3.y, acc.y);
        acc.z = fmaf(w3, v3.z, acc.z); acc.w = fmaf(w3, v3.w, acc.w);
    }
    for (; i < e; i++) {
        int   c = __ldg(&g_colS[i]);
        float w = __ldg(&g_wS[i]);
        float4 v = __ldg(reinterpret_cast<const float4*>(support + (size_t)c * NHID) + lane);
        acc.x = fmaf(w, v.x, acc.x); acc.y = fmaf(w, v.y, acc.y);
        acc.z = fmaf(w, v.z, acc.z); acc.w = fmaf(w, v.w, acc.w);
    }
    float4 b = __ldg(reinterpret_cast<const float4*>(bias) + lane);
    acc.x = fmaxf(acc.x + b.x, 0.f);
    acc.y = fmaxf(acc.y + b.y, 0.f);
    acc.z = fmaxf(acc.z + b.z, 0.f);
    acc.w = fmaxf(acc.w + b.w, 0.f);
    *(reinterpret_cast<float4*>(out + (size_t)warp * NHID) + lane) = acc;
}

// ---------------------------------------------------------------------------
// Tiled SGEMM: C[M,Nc] = A[M,K] @ B[K,Nc] (+bias), row-major.
// HEADS=true: Nc=128 logical, split-store halves to mu/log_var regions.
// ---------------------------------------------------------------------------
template <int BM, int BN, int BK, int TM, int TN, bool HEADS>
__global__ __launch_bounds__(256) void sgemm_kernel(
    const float* __restrict__ A, const float* __restrict__ B,
    const float* __restrict__ bias, float* __restrict__ C,
    int M, int Nc, int K)
{
    __shared__ float As[BK][BM];
    __shared__ float Bs[BK][BN];

    const int tid  = threadIdx.x;
    const int tcol = tid % (BN / TN);
    const int trow = tid / (BN / TN);
    const int blockRow = blockIdx.y * BM;
    const int blockCol = blockIdx.x * BN;

    float acc[TM][TN];
#pragma unroll
    for (int i = 0; i < TM; i++)
#pragma unroll
        for (int j = 0; j < TN; j++) acc[i][j] = 0.f;

    const int aRow0 = tid / (BK / 4);
    const int aCol4 = (tid % (BK / 4)) * 4;
    const int bRow0 = tid / (BN / 4);
    const int bCol4 = (tid % (BN / 4)) * 4;

    for (int k0 = 0; k0 < K; k0 += BK) {
#pragma unroll
        for (int i = 0; i < BM; i += 256 / (BK / 4)) {
            int r = aRow0 + i;
            int grow = blockRow + r;
            float4 v = make_float4(0.f, 0.f, 0.f, 0.f);
            if (grow < M)
                v = *reinterpret_cast<const float4*>(A + (size_t)grow * K + k0 + aCol4);
            As[aCol4 + 0][r] = v.x;
            As[aCol4 + 1][r] = v.y;
            As[aCol4 + 2][r] = v.z;
            As[aCol4 + 3][r] = v.w;
        }
#pragma unroll
        for (int i = 0; i < BK; i += 256 / (BN / 4)) {
            int r = bRow0 + i;
            int gcol = blockCol + bCol4;
            float4 v = make_float4(0.f, 0.f, 0.f, 0.f);
            if (gcol < Nc)
                v = *reinterpret_cast<const float4*>(B + (size_t)(k0 + r) * Nc + gcol);
            *reinterpret_cast<float4*>(&Bs[r][bCol4]) = v;
        }
        __syncthreads();

#pragma unroll
        for (int k = 0; k < BK; k++) {
            float ra[TM], rb[TN];
            *reinterpret_cast<float4*>(&ra[0]) =
                *reinterpret_cast<const float4*>(&As[k][trow * TM + 0]);
            *reinterpret_cast<float4*>(&ra[4]) =
                *reinterpret_cast<const float4*>(&As[k][trow * TM + 4]);
            *reinterpret_cast<float4*>(&rb[0]) =
                *reinterpret_cast<const float4*>(&Bs[k][tcol * TN + 0]);
            *reinterpret_cast<float4*>(&rb[4]) =
                *reinterpret_cast<const float4*>(&Bs[k][tcol * TN + 4]);
#pragma unroll
            for (int i = 0; i < TM; i++)
#pragma unroll
                for (int j = 0; j < TN; j++)
                    acc[i][j] = fmaf(ra[i], rb[j], acc[i][j]);
        }
        __syncthreads();
    }

#pragma unroll
    for (int i = 0; i < TM; i++) {
        int grow = blockRow + trow * TM + i;
        if (grow >= M) continue;
#pragma unroll
        for (int j = 0; j < TN; j += 4) {
            int gcol = blockCol + tcol * TN + j;
            if (gcol < Nc) {
                float4 v;
                v.x = acc[i][j + 0] + (bias ? bias[gcol + 0] : 0.f);
                v.y = acc[i][j + 1] + (bias ? bias[gcol + 1] : 0.f);
                v.z = acc[i][j + 2] + (bias ? bias[gcol + 2] : 0.f);
                v.w = acc[i][j + 3] + (bias ? bias[gcol + 3] : 0.f);
                if (HEADS) {
                    // cols [0,64) -> mu at C[0]; cols [64,128) -> log_var at C[NN*64]
                    size_t off = (gcol < LATENT)
                               ? (size_t)grow * LATENT + gcol
                               : (size_t)NN * LATENT + (size_t)grow * LATENT + (gcol - LATENT);
                    *reinterpret_cast<float4*>(C + off) = v;
                } else {
                    *reinterpret_cast<float4*>(C + (size_t)grow * Nc + gcol) = v;
                }
            }
        }
    }
}

// Build concatenated head weights [128,128] and bias [128]
__global__ __launch_bounds__(256) void concat_heads(
    const float* __restrict__ mu_w, const float* __restrict__ lv_w,
    const float* __restrict__ mu_b, const float* __restrict__ lv_b)
{
    int i = blockIdx.x * blockDim.x + threadIdx.x;
    if (i < NHID * NHID) {
        int k = i >> 7, j = i & 127;
        g_wcat[i] = (j < LATENT) ? mu_w[k * LATENT + j] : lv_w[k * LATENT + j - LATENT];
    }
    if (i < NHID)
        g_bcat[i] = (i < LATENT) ? mu_b[i] : lv_b[i - LATENT];
}

extern "C" void kernel_launch(void* const* d_in, const int* in_sizes, int n_in,
                              void* d_out, int out_size)
{
    const float* x      = (const float*)d_in[0];
    const int*   ei     = (const int*)  d_in[1];
    const float* ew     = (const float*)d_in[2];
    const float* gc1_w  = (const float*)d_in[3];
    const float* gc1_b  = (const float*)d_in[4];
    const float* gc2_w  = (const float*)d_in[5];
    const float* gc2_b  = (const float*)d_in[6];
    const float* mu_w   = (const float*)d_in[7];
    const float* mu_b   = (const float*)d_in[8];
    const float* lv_w   = (const float*)d_in[9];
    const float* lv_b   = (const float*)d_in[10];
    float* out = (float*)d_out;

    float *A, *B, *wcat, *bcat;
    int *cnt;
    cudaGetSymbolAddress((void**)&A, g_bufA);
    cudaGetSymbolAddress((void**)&B, g_bufB);
    cudaGetSymbolAddress((void**)&cnt, g_cnt);
    cudaGetSymbolAddress((void**)&wcat, g_wcat);
    cudaGetSymbolAddress((void**)&bcat, g_bcat);

    const dim3 gGemm128(1, (NN + 127) / 128);
    const int edgeBlocks = (EE + 255) / 256;
    const int spmmBlocks = (NN * 32 + 255) / 256;

    // ---- CSR build (reused by both spmm layers) ----
    cudaMemsetAsync(cnt, 0, NN * sizeof(int));
    hist_kernel<<<edgeBlocks, 256>>>(ei);
    scan1_kernel<<<NSCANBLK, 256>>>();
    scan2_kernel<<<1, 32>>>();
    scan3_kernel<<<(NTOT + 255) / 256, 256>>>();
    cudaMemsetAsync(cnt, 0, NN * sizeof(int));
    scatter_kernel<<<edgeBlocks, 256>>>(ei, ew);

    // ---- Layer 1 ----
    sgemm_kernel<128, 128, 16, 8, 8, false><<<gGemm128, 256>>>(x, gc1_w, nullptr, A, NN, NHID, NFEAT);
    spmm_csr_bias_relu<<<spmmBlocks, 256>>>(A, gc1_b, B);   // B = h1

    // ---- Layer 2 ----
    sgemm_kernel<128, 128, 16, 8, 8, false><<<gGemm128, 256>>>(B, gc2_w, nullptr, A, NN, NHID, NHID);
    spmm_csr_bias_relu<<<spmmBlocks, 256>>>(A, gc2_b, B);   // B = h2

    // ---- Fused heads: [mu | log_var] = h2 @ [mu_w | lv_w] + [mu_b | lv_b] ----
    concat_heads<<<(NHID * NHID + 255) / 256, 256>>>(mu_w, lv_w, mu_b, lv_b);
    sgemm_kernel<128, 128, 16, 8, 8, true><<<gGemm128, 256>>>(B, wcat, bcat, out, NN, NHID, NHID);
}

// round 4
// speedup vs baseline: 1.8210x; 1.0860x over previous
#include <cuda_runtime.h>
#include <cuda_fp16.h>
#include <cstdint>

// Problem constants
#define NN 100000
#define EE 1600000
#define NFEAT 256
#define NHID 128
#define LATENT 64
#define SCAN_CHUNK 2048
#define NTOT (NN + 1)
#define NSCANBLK ((NTOT + SCAN_CHUNK - 1) / SCAN_CHUNK)

// Scratch (allocation-free rule: __device__ globals)
__device__ float  g_bufA[(size_t)NN * NHID];   // fp32 h1/h2
__device__ __half g_bufH[(size_t)NN * NHID];   // fp16 support (gemm out -> spmm in)
__device__ int    g_cnt[NN];
__device__ int    g_rowptr[NTOT];
__device__ int    g_blocksums[NSCANBLK + 1];
__device__ int    g_colS[EE];
__device__ float  g_wS[EE];
__device__ float  g_wcat[NHID * NHID];
__device__ float  g_bcat[NHID];

// ---------------------------------------------------------------------------
// CSR build: histogram -> exclusive scan -> scatter
// ---------------------------------------------------------------------------
__global__ __launch_bounds__(256) void hist_kernel(const int* __restrict__ ei)
{
    int e = blockIdx.x * blockDim.x + threadIdx.x;
    if (e < EE) atomicAdd(&g_cnt[ei[e]], 1);
}

__global__ __launch_bounds__(256) void scan1_kernel()
{
    __shared__ int sh[256];
    int b = blockIdx.x, t = threadIdx.x;
    int base = b * SCAN_CHUNK + t * 8;
    int v[8];
    int sum = 0;
#pragma unroll
    for (int k = 0; k < 8; k++) {
        int idx = base + k;
        int c = (idx < NN) ? g_cnt[idx] : 0;
        v[k] = sum;
        sum += c;
    }
    sh[t] = sum;
    __syncthreads();
    for (int off = 1; off < 256; off <<= 1) {
        int x = (t >= off) ? sh[t - off] : 0;
        __syncthreads();
        sh[t] += x;
        __syncthreads();
    }
    int threadExcl = sh[t] - sum;
#pragma unroll
    for (int k = 0; k < 8; k++) {
        int idx = base + k;
        if (idx < NTOT) g_rowptr[idx] = threadExcl + v[k];
    }
    if (t == 255) g_blocksums[b] = sh[255];
}

__global__ void scan2_kernel()
{
    if (threadIdx.x == 0) {
        int s = 0;
        for (int i = 0; i < NSCANBLK; i++) {
            int c = g_blocksums[i];
            g_blocksums[i] = s;
            s += c;
        }
    }
}

__global__ __launch_bounds__(256) void scan3_kernel()
{
    int i = blockIdx.x * blockDim.x + threadIdx.x;
    if (i < NTOT) g_rowptr[i] += g_blocksums[i / SCAN_CHUNK];
}

__global__ __launch_bounds__(256) void scatter_kernel(
    const int* __restrict__ ei, const float* __restrict__ ew)
{
    int e = blockIdx.x * blockDim.x + threadIdx.x;
    if (e >= EE) return;
    int r = ei[e];
    int pos = g_rowptr[r] + atomicAdd(&g_cnt[r], 1);
    g_colS[pos] = ei[EE + e];
    g_wS[pos]   = ew[e];
}

// ---------------------------------------------------------------------------
// CSR SpMM (fp16 support) fused with bias + ReLU: one warp per row.
// Each lane gathers 4 halves (8B) per edge; fp32 accumulation.
// ---------------------------------------------------------------------------
__global__ __launch_bounds__(256) void spmm_csr_bias_relu(
    const __half* __restrict__ support, const float* __restrict__ bias,
    float* __restrict__ out)
{
    int warp = (blockIdx.x * blockDim.x + threadIdx.x) >> 5;
    if (warp >= NN) return;
    int lane = threadIdx.x & 31;

    int s = __ldg(&g_rowptr[warp]);
    int e = __ldg(&g_rowptr[warp + 1]);

    float4 acc = make_float4(0.f, 0.f, 0.f, 0.f);
    int i = s;
    for (; i + 4 <= e; i += 4) {
        int   c0 = __ldg(&g_colS[i]),     c1 = __ldg(&g_colS[i + 1]);
        int   c2 = __ldg(&g_colS[i + 2]), c3 = __ldg(&g_colS[i + 3]);
        float w0 = __ldg(&g_wS[i]),       w1 = __ldg(&g_wS[i + 1]);
        float w2 = __ldg(&g_wS[i + 2]),   w3 = __ldg(&g_wS[i + 3]);
        uint2 r0 = __ldg(reinterpret_cast<const uint2*>(support + (size_t)c0 * NHID) + lane);
        uint2 r1 = __ldg(reinterpret_cast<const uint2*>(support + (size_t)c1 * NHID) + lane);
        uint2 r2 = __ldg(reinterpret_cast<const uint2*>(support + (size_t)c2 * NHID) + lane);
        uint2 r3 = __ldg(reinterpret_cast<const uint2*>(support + (size_t)c3 * NHID) + lane);
        float2 a0 = __half22float2(*reinterpret_cast<__half2*>(&r0.x));
        float2 b0 = __half22float2(*reinterpret_cast<__half2*>(&r0.y));
        float2 a1 = __half22float2(*reinterpret_cast<__half2*>(&r1.x));
        float2 b1 = __half22float2(*reinterpret_cast<__half2*>(&r1.y));
        float2 a2 = __half22float2(*reinterpret_cast<__half2*>(&r2.x));
        float2 b2 = __half22float2(*reinterpret_cast<__half2*>(&r2.y));
        float2 a3 = __half22float2(*reinterpret_cast<__half2*>(&r3.x));
        float2 b3 = __half22float2(*reinterpret_cast<__half2*>(&r3.y));
        acc.x = fmaf(w0, a0.x, acc.x); acc.y = fmaf(w0, a0.y, acc.y);
        acc.z = fmaf(w0, b0.x, acc.z); acc.w = fmaf(w0, b0.y, acc.w);
        acc.x = fmaf(w1, a1.x, acc.x); acc.y = fmaf(w1, a1.y, acc.y);
        acc.z = fmaf(w1, b1.x, acc.z); acc.w = fmaf(w1, b1.y, acc.w);
        acc.x = fmaf(w2, a2.x, acc.x); acc.y = fmaf(w2, a2.y, acc.y);
        acc.z = fmaf(w2, b2.x, acc.z); acc.w = fmaf(w2, b2.y, acc.w);
        acc.x = fmaf(w3, a3.x, acc.x); acc.y = fmaf(w3, a3.y, acc.y);
        acc.z = fmaf(w3, b3.x, acc.z); acc.w = fmaf(w3, b3.y, acc.w);
    }
    for (; i < e; i++) {
        int   c = __ldg(&g_colS[i]);
        float w = __ldg(&g_wS[i]);
        uint2 r = __ldg(reinterpret_cast<const uint2*>(support + (size_t)c * NHID) + lane);
        float2 a = __half22float2(*reinterpret_cast<__half2*>(&r.x));
        float2 b = __half22float2(*reinterpret_cast<__half2*>(&r.y));
        acc.x = fmaf(w, a.x, acc.x); acc.y = fmaf(w, a.y, acc.y);
        acc.z = fmaf(w, b.x, acc.z); acc.w = fmaf(w, b.y, acc.w);
    }
    float4 b = __ldg(reinterpret_cast<const float4*>(bias) + lane);
    acc.x = fmaxf(acc.x + b.x, 0.f);
    acc.y = fmaxf(acc.y + b.y, 0.f);
    acc.z = fmaxf(acc.z + b.z, 0.f);
    acc.w = fmaxf(acc.w + b.w, 0.f);
    *(reinterpret_cast<float4*>(out + (size_t)warp * NHID) + lane) = acc;
}

// ---------------------------------------------------------------------------
// Tiled SGEMM: C[M,Nc] = A[M,K] @ B[K,Nc] (+bias), row-major.
// OUT_HALF: store fp16 (support buffers). HEADS: split-store mu/log_var.
// ---------------------------------------------------------------------------
template <int BM, int BN, int BK, int TM, int TN, bool OUT_HALF, bool HEADS>
__global__ __launch_bounds__(256) void sgemm_kernel(
    const float* __restrict__ A, const float* __restrict__ B,
    const float* __restrict__ bias, void* __restrict__ Cv,
    int M, int Nc, int K)
{
    __shared__ float As[BK][BM];
    __shared__ float Bs[BK][BN];

    const int tid  = threadIdx.x;
    const int tcol = tid % (BN / TN);
    const int trow = tid / (BN / TN);
    const int blockRow = blockIdx.y * BM;
    const int blockCol = blockIdx.x * BN;

    float acc[TM][TN];
#pragma unroll
    for (int i = 0; i < TM; i++)
#pragma unroll
        for (int j = 0; j < TN; j++) acc[i][j] = 0.f;

    const int aRow0 = tid / (BK / 4);
    const int aCol4 = (tid % (BK / 4)) * 4;
    const int bRow0 = tid / (BN / 4);
    const int bCol4 = (tid % (BN / 4)) * 4;

    for (int k0 = 0; k0 < K; k0 += BK) {
#pragma unroll
        for (int i = 0; i < BM; i += 256 / (BK / 4)) {
            int r = aRow0 + i;
            int grow = blockRow + r;
            float4 v = make_float4(0.f, 0.f, 0.f, 0.f);
            if (grow < M)
                v = *reinterpret_cast<const float4*>(A + (size_t)grow * K + k0 + aCol4);
            As[aCol4 + 0][r] = v.x;
            As[aCol4 + 1][r] = v.y;
            As[aCol4 + 2][r] = v.z;
            As[aCol4 + 3][r] = v.w;
        }
#pragma unroll
        for (int i = 0; i < BK; i += 256 / (BN / 4)) {
            int r = bRow0 + i;
            int gcol = blockCol + bCol4;
            float4 v = make_float4(0.f, 0.f, 0.f, 0.f);
            if (gcol < Nc)
                v = *reinterpret_cast<const float4*>(B + (size_t)(k0 + r) * Nc + gcol);
            *reinterpret_cast<float4*>(&Bs[r][bCol4]) = v;
        }
        __syncthreads();

#pragma unroll
        for (int k = 0; k < BK; k++) {
            float ra[TM], rb[TN];
            *reinterpret_cast<float4*>(&ra[0]) =
                *reinterpret_cast<const float4*>(&As[k][trow * TM + 0]);
            *reinterpret_cast<float4*>(&ra[4]) =
                *reinterpret_cast<const float4*>(&As[k][trow * TM + 4]);
            *reinterpret_cast<float4*>(&rb[0]) =
                *reinterpret_cast<const float4*>(&Bs[k][tcol * TN + 0]);
            *reinterpret_cast<float4*>(&rb[4]) =
                *reinterpret_cast<const float4*>(&Bs[k][tcol * TN + 4]);
#pragma unroll
            for (int i = 0; i < TM; i++)
#pragma unroll
                for (int j = 0; j < TN; j++)
                    acc[i][j] = fmaf(ra[i], rb[j], acc[i][j]);
        }
        __syncthreads();
    }

#pragma unroll
    for (int i = 0; i < TM; i++) {
        int grow = blockRow + trow * TM + i;
        if (grow >= M) continue;
#pragma unroll
        for (int j = 0; j < TN; j += 4) {
            int gcol = blockCol + tcol * TN + j;
            if (gcol >= Nc) continue;
            float4 v;
            v.x = acc[i][j + 0] + (bias ? bias[gcol + 0] : 0.f);
            v.y = acc[i][j + 1] + (bias ? bias[gcol + 1] : 0.f);
            v.z = acc[i][j + 2] + (bias ? bias[gcol + 2] : 0.f);
            v.w = acc[i][j + 3] + (bias ? bias[gcol + 3] : 0.f);
            if (OUT_HALF) {
                __half2 p0 = __floats2half2_rn(v.x, v.y);
                __half2 p1 = __floats2half2_rn(v.z, v.w);
                uint2 st;
                st.x = *reinterpret_cast<uint32_t*>(&p0);
                st.y = *reinterpret_cast<uint32_t*>(&p1);
                *reinterpret_cast<uint2*>(
                    reinterpret_cast<__half*>(Cv) + (size_t)grow * Nc + gcol) = st;
            } else if (HEADS) {
                float* C = reinterpret_cast<float*>(Cv);
                size_t off = (gcol < LATENT)
                           ? (size_t)grow * LATENT + gcol
                           : (size_t)NN * LATENT + (size_t)grow * LATENT + (gcol - LATENT);
                *reinterpret_cast<float4*>(C + off) = v;
            } else {
                float* C = reinterpret_cast<float*>(Cv);
                *reinterpret_cast<float4*>(C + (size_t)grow * Nc + gcol) = v;
            }
        }
    }
}

// Build concatenated head weights [128,128] and bias [128]
__global__ __launch_bounds__(256) void concat_heads(
    const float* __restrict__ mu_w, const float* __restrict__ lv_w,
    const float* __restrict__ mu_b, const float* __restrict__ lv_b)
{
    int i = blockIdx.x * blockDim.x + threadIdx.x;
    if (i < NHID * NHID) {
        int k = i >> 7, j = i & 127;
        g_wcat[i] = (j < LATENT) ? mu_w[k * LATENT + j] : lv_w[k * LATENT + j - LATENT];
    }
    if (i < NHID)
        g_bcat[i] = (i < LATENT) ? mu_b[i] : lv_b[i - LATENT];
}

extern "C" void kernel_launch(void* const* d_in, const int* in_sizes, int n_in,
                              void* d_out, int out_size)
{
    const float* x      = (const float*)d_in[0];
    const int*   ei     = (const int*)  d_in[1];
    const float* ew     = (const float*)d_in[2];
    const float* gc1_w  = (const float*)d_in[3];
    const float* gc1_b  = (const float*)d_in[4];
    const float* gc2_w  = (const float*)d_in[5];
    const float* gc2_b  = (const float*)d_in[6];
    const float* mu_w   = (const float*)d_in[7];
    const float* mu_b   = (const float*)d_in[8];
    const float* lv_w   = (const float*)d_in[9];
    const float* lv_b   = (const float*)d_in[10];
    float* out = (float*)d_out;

    float *A, *wcat, *bcat;
    __half *H;
    int *cnt;
    cudaGetSymbolAddress((void**)&A, g_bufA);
    cudaGetSymbolAddress((void**)&H, g_bufH);
    cudaGetSymbolAddress((void**)&cnt, g_cnt);
    cudaGetSymbolAddress((void**)&wcat, g_wcat);
    cudaGetSymbolAddress((void**)&bcat, g_bcat);

    const dim3 gGemm128(1, (NN + 127) / 128);
    const int edgeBlocks = (EE + 255) / 256;
    const int spmmBlocks = (NN * 32 + 255) / 256;

    // ---- CSR build (reused by both spmm layers) ----
    cudaMemsetAsync(cnt, 0, NN * sizeof(int));
    hist_kernel<<<edgeBlocks, 256>>>(ei);
    scan1_kernel<<<NSCANBLK, 256>>>();
    scan2_kernel<<<1, 32>>>();
    scan3_kernel<<<(NTOT + 255) / 256, 256>>>();
    cudaMemsetAsync(cnt, 0, NN * sizeof(int));
    scatter_kernel<<<edgeBlocks, 256>>>(ei, ew);

    // ---- Layer 1: support(fp16) = x @ gc1_w ; h1 = relu(spmm + b1) ----
    sgemm_kernel<128, 128, 16, 8, 8, true, false><<<gGemm128, 256>>>(x, gc1_w, nullptr, H, NN, NHID, NFEAT);
    spmm_csr_bias_relu<<<spmmBlocks, 256>>>(H, gc1_b, A);   // A = h1 (fp32)

    // ---- Layer 2 ----
    sgemm_kernel<128, 128, 16, 8, 8, true, false><<<gGemm128, 256>>>(A, gc2_w, nullptr, H, NN, NHID, NHID);
    spmm_csr_bias_relu<<<spmmBlocks, 256>>>(H, gc2_b, A);   // A = h2 (fp32)

    // ---- Fused heads: [mu | log_var] = h2 @ [mu_w | lv_w] + [mu_b | lv_b] ----
    concat_heads<<<(NHID * NHID + 255) / 256, 256>>>(mu_w, lv_w, mu_b, lv_b);
    sgemm_kernel<128, 128, 16, 8, 8, false, true><<<gGemm128, 256>>>(A, wcat, bcat, out, NN, NHID, NHID);
}

// round 9
// speedup vs baseline: 3.3403x; 1.8343x over previous
#include <cuda_runtime.h>
#include <cuda_fp16.h>
#include <cstdint>

// Problem constants
#define NN 100000
#define EE 1600000
#define NFEAT 256
#define NHID 128
#define LATENT 64
#define SCAN_CHUNK 2048
#define NTOT (NN + 1)
#define NSCANBLK ((NTOT + SCAN_CHUNK - 1) / SCAN_CHUNK)

// Scratch (allocation-free rule: __device__ globals)
__device__ __half g_xh[(size_t)NN * NFEAT];    // fp16 x
__device__ __half g_sup[(size_t)NN * NHID];    // fp16 support (gemm out -> spmm in)
__device__ __half g_h[(size_t)NN * NHID];      // fp16 h1/h2 (spmm out -> gemm in)
__device__ __half g_w1t[NHID * NFEAT];         // W1^T [128,256] fp16
__device__ __half g_w2t[NHID * NHID];          // W2^T [128,128] fp16
__device__ __half g_wct[NHID * NHID];          // [mu|lv]^T [128,128] fp16
__device__ float  g_bcatf[NHID];
__device__ int    g_cnt[NN];
__device__ int    g_rowptr[NTOT];
__device__ int    g_blocksums[NSCANBLK + 1];
__device__ int    g_colS[EE];
__device__ float  g_wS[EE];

// ===========================================================================
// mma.sync helpers
// ===========================================================================
__device__ __forceinline__ uint32_t smem_to_u32(const void* p) {
    uint32_t a;
    asm("{ .reg .u64 t; cvta.to.shared.u64 t, %1; cvt.u32.u64 %0, t; }"
        : "=r"(a) : "l"(p));
    return a;
}

__device__ __forceinline__ void ldsm_x4(uint32_t& r0, uint32_t& r1,
                                        uint32_t& r2, uint32_t& r3, uint32_t addr)
{
    asm volatile("ldmatrix.sync.aligned.m8n8.x4.shared.b16 {%0,%1,%2,%3}, [%4];"
                 : "=r"(r0), "=r"(r1), "=r"(r2), "=r"(r3) : "r"(addr));
}

__device__ __forceinline__ void mma16816(float* c, const uint32_t* a, const uint32_t* b)
{
    asm volatile(
        "mma.sync.aligned.m16n8k16.row.col.f32.f16.f16.f32 "
        "{%0,%1,%2,%3}, {%4,%5,%6,%7}, {%8,%9}, {%0,%1,%2,%3};"
        : "+f"(c[0]), "+f"(c[1]), "+f"(c[2]), "+f"(c[3])
        : "r"(a[0]), "r"(a[1]), "r"(a[2]), "r"(a[3]), "r"(b[0]), "r"(b[1]));
}

// ===========================================================================
// HMMA GEMM: C[M,128] = A[M,KDIM](fp16) @ Bt[128,KDIM]^T (fp16), fp32 acc.
// CTA: 256 thr = 8 warps (4 warpRow x 2 warpCol); warp tile 32x64.
// HEADS=false -> fp16 store; HEADS=true -> fp32 +bias split mu/log_var.
// ===========================================================================
#define ROWP 24   // padded row stride in halves (48B): conflict-free ldmatrix

template <int KDIM, bool HEADS>
__global__ __launch_bounds__(256) void mma_gemm(
    const __half* __restrict__ A, const __half* __restrict__ Bt,
    const float* __restrict__ bias, void* __restrict__ outv, int M)
{
    __shared__ __align__(16) __half sA[128 * ROWP];
    __shared__ __align__(16) __half sB[128 * ROWP];

    const int tid  = threadIdx.x;
    const int warp = tid >> 5, lane = tid & 31;
    const int warpM = (warp >> 1) * 32;      // 0,32,64,96
    const int warpN = (warp & 1) * 64;       // 0,64
    const int blockRow = blockIdx.x * 128;

    const uint32_t sAb = smem_to_u32(sA);
    const uint32_t sBb = smem_to_u32(sB);

    float acc[2][8][4];
#pragma unroll
    for (int i = 0; i < 2; i++)
#pragma unroll
        for (int j = 0; j < 8; j++)
#pragma unroll
            for (int k = 0; k < 4; k++) acc[i][j][k] = 0.f;

    // Stage loader indices: thread t -> row t/2, 8-half chunk t%2
    const int ldRow = tid >> 1;
    const int ldChunk = (tid & 1) * 8;
    const int gRowA = blockRow + ldRow;

    // ldmatrix lane addresses (byte offsets within tile)
    // A (x4): row = warpM + (lane&15), chunk = (lane>>4)*8
    //   -> r0..r3 = a0..a3 of the two 16x16 halves handled below via mi*16
    const uint32_t aOffBase =
        (uint32_t)(warpM + (lane & 15)) * (ROWP * 2) + (uint32_t)((lane >> 4) * 16);
    // B (x4, NON-trans; Bt is [n][k] row-major = mma "col" layout):
    //   lanes 0-7:  n = warpN+0..7,  k-chunk 0   (matrix0 -> b0, n-group 0)
    //   lanes 8-15: n = warpN+0..7,  k-chunk 8   (matrix1 -> b1, n-group 0)
    //   lanes 16-23: n = warpN+8..15, k-chunk 0  (matrix2 -> b0, n-group 1)
    //   lanes 24-31: n = warpN+8..15, k-chunk 8  (matrix3 -> b1, n-group 1)
    const uint32_t bOffBase =
        (uint32_t)(warpN + ((lane >> 4) << 3) + (lane & 7)) * (ROWP * 2)
        + (uint32_t)(((lane >> 3) & 1) * 16);

#pragma unroll 1
    for (int k0 = 0; k0 < KDIM; k0 += 16) {
        // Stage A and B 128x16 tiles
        uint4 va = make_uint4(0u, 0u, 0u, 0u);
        if (gRowA < M)
            va = *reinterpret_cast<const uint4*>(A + (size_t)gRowA * KDIM + k0 + ldChunk);
        *reinterpret_cast<uint4*>(sA + ldRow * ROWP + ldChunk) = va;
        uint4 vb = *reinterpret_cast<const uint4*>(Bt + (size_t)ldRow * KDIM + k0 + ldChunk);
        *reinterpret_cast<uint4*>(sB + ldRow * ROWP + ldChunk) = vb;
        __syncthreads();

        uint32_t af[2][4];
#pragma unroll
        for (int mi = 0; mi < 2; mi++)
            ldsm_x4(af[mi][0], af[mi][1], af[mi][2], af[mi][3],
                    sAb + aOffBase + (uint32_t)mi * 16 * (ROWP * 2));

        uint32_t bf[8][2];
#pragma unroll
        for (int nj = 0; nj < 4; nj++) {
            uint32_t b0, b1, b2, b3;
            ldsm_x4(b0, b1, b2, b3,
                    sBb + bOffBase + (uint32_t)nj * 16 * (ROWP * 2));
            bf[nj * 2][0] = b0;     bf[nj * 2][1] = b1;
            bf[nj * 2 + 1][0] = b2; bf[nj * 2 + 1][1] = b3;
        }

#pragma unroll
        for (int mi = 0; mi < 2; mi++)
#pragma unroll
            for (int ni = 0; ni < 8; ni++)
                mma16816(acc[mi][ni], af[mi], bf[ni]);
        __syncthreads();
    }

    // Epilogue: documented c-frag layout (g=lane>>2, tg=lane&3)
    const int g = lane >> 2, tg = lane & 3;
#pragma unroll
    for (int mi = 0; mi < 2; mi++) {
        int r0 = blockRow + warpM + mi * 16 + g;      // rows r0 and r0+8
#pragma unroll
        for (int ni = 0; ni < 8; ni++) {
            int col = warpN + ni * 8 + tg * 2;
            if (HEADS) {
                float* out = reinterpret_cast<float*>(outv);
                size_t regionOff = (col < LATENT) ? 0 : (size_t)NN * LATENT;
                int c0 = col & (LATENT - 1);
                float bx = bias[col], by = bias[col + 1];
                if (r0 < M) {
                    float2 v = make_float2(acc[mi][ni][0] + bx, acc[mi][ni][1] + by);
                    *reinterpret_cast<float2*>(out + regionOff + (size_t)r0 * LATENT + c0) = v;
                }
                if (r0 + 8 < M) {
                    float2 v = make_float2(acc[mi][ni][2] + bx, acc[mi][ni][3] + by);
                    *reinterpret_cast<float2*>(out + regionOff + (size_t)(r0 + 8) * LATENT + c0) = v;
                }
            } else {
                __half* out = reinterpret_cast<__half*>(outv);
                if (r0 < M) {
                    __half2 h = __floats2half2_rn(acc[mi][ni][0], acc[mi][ni][1]);
                    *reinterpret_cast<__half2*>(out + (size_t)r0 * NHID + col) = h;
                }
                if (r0 + 8 < M) {
                    __half2 h = __floats2half2_rn(acc[mi][ni][2], acc[mi][ni][3]);
                    *reinterpret_cast<__half2*>(out + (size_t)(r0 + 8) * NHID + col) = h;
                }
            }
        }
    }
}

// ===========================================================================
// Prep kernels
// ===========================================================================
__global__ __launch_bounds__(256) void convert_x(const float* __restrict__ x)
{
    size_t i = (size_t)blockIdx.x * blockDim.x + threadIdx.x;   // 8 floats per thread
    size_t base = i * 8;
    if (base >= (size_t)NN * NFEAT) return;
    float4 a = *reinterpret_cast<const float4*>(x + base);
    float4 b = *reinterpret_cast<const float4*>(x + base + 4);
    __half2 p0 = __floats2half2_rn(a.x, a.y);
    __half2 p1 = __floats2half2_rn(a.z, a.w);
    __half2 p2 = __floats2half2_rn(b.x, b.y);
    __half2 p3 = __floats2half2_rn(b.z, b.w);
    uint4 st;
    st.x = *reinterpret_cast<uint32_t*>(&p0);
    st.y = *reinterpret_cast<uint32_t*>(&p1);
    st.z = *reinterpret_cast<uint32_t*>(&p2);
    st.w = *reinterpret_cast<uint32_t*>(&p3);
    *reinterpret_cast<uint4*>(g_xh + base) = st;
}

__global__ __launch_bounds__(256) void prep_weights(
    const float* __restrict__ gc1_w, const float* __restrict__ gc2_w,
    const float* __restrict__ mu_w, const float* __restrict__ lv_w,
    const float* __restrict__ mu_b, const float* __restrict__ lv_b)
{
    int i = blockIdx.x * blockDim.x + threadIdx.x;
    if (i < NHID * NFEAT) {         // w1t[n,k] = gc1_w[k,n]
        int n = i / NFEAT, k = i % NFEAT;
        g_w1t[i] = __float2half_rn(gc1_w[k * NHID + n]);
    }
    if (i < NHID * NHID) {          // w2t / wct
        int n = i / NHID, k = i % NHID;
        g_w2t[i] = __float2half_rn(gc2_w[k * NHID + n]);
        g_wct[i] = __float2half_rn(n < LATENT ? mu_w[k * LATENT + n]
                                              : lv_w[k * LATENT + n - LATENT]);
    }
    if (i < NHID)
        g_bcatf[i] = (i < LATENT) ? mu_b[i] : lv_b[i - LATENT];
}

// ===========================================================================
// CSR build: histogram -> exclusive scan -> scatter
// ===========================================================================
__global__ __launch_bounds__(256) void hist_kernel(const int* __restrict__ ei)
{
    int e = blockIdx.x * blockDim.x + threadIdx.x;
    if (e < EE) atomicAdd(&g_cnt[ei[e]], 1);
}

__global__ __launch_bounds__(256) void scan1_kernel()
{
    __shared__ int sh[256];
    int b = blockIdx.x, t = threadIdx.x;
    int base = b * SCAN_CHUNK + t * 8;
    int v[8];
    int sum = 0;
#pragma unroll
    for (int k = 0; k < 8; k++) {
        int idx = base + k;
        int c = (idx < NN) ? g_cnt[idx] : 0;
        v[k] = sum;
        sum += c;
    }
    sh[t] = sum;
    __syncthreads();
    for (int off = 1; off < 256; off <<= 1) {
        int x = (t >= off) ? sh[t - off] : 0;
        __syncthreads();
        sh[t] += x;
        __syncthreads();
    }
    int threadExcl = sh[t] - sum;
#pragma unroll
    for (int k = 0; k < 8; k++) {
        int idx = base + k;
        if (idx < NTOT) g_rowptr[idx] = threadExcl + v[k];
    }
    if (t == 255) g_blocksums[b] = sh[255];
}

__global__ void scan2_kernel()
{
    if (threadIdx.x == 0) {
        int s = 0;
        for (int i = 0; i < NSCANBLK; i++) {
            int c = g_blocksums[i];
            g_blocksums[i] = s;
            s += c;
        }
    }
}

__global__ __launch_bounds__(256) void scan3_kernel()
{
    int i = blockIdx.x * blockDim.x + threadIdx.x;
    if (i < NTOT) g_rowptr[i] += g_blocksums[i / SCAN_CHUNK];
}

__global__ __launch_bounds__(256) void scatter_kernel(
    const int* __restrict__ ei, const float* __restrict__ ew)
{
    int e = blockIdx.x * blockDim.x + threadIdx.x;
    if (e >= EE) return;
    int r = ei[e];
    int pos = g_rowptr[r] + atomicAdd(&g_cnt[r], 1);
    g_colS[pos] = ei[EE + e];
    g_wS[pos]   = ew[e];
}

// ===========================================================================
// CSR SpMM (fp16 support in, fp16 h out) fused bias + ReLU, fp32 accumulate.
// ===========================================================================
__global__ __launch_bounds__(256) void spmm_csr_bias_relu(
    const __half* __restrict__ support, const float* __restrict__ bias,
    __half* __restrict__ out)
{
    int warp = (blockIdx.x * blockDim.x + threadIdx.x) >> 5;
    if (warp >= NN) return;
    int lane = threadIdx.x & 31;

    int s = __ldg(&g_rowptr[warp]);
    int e = __ldg(&g_rowptr[warp + 1]);

    float4 acc = make_float4(0.f, 0.f, 0.f, 0.f);
    int i = s;
    for (; i + 4 <= e; i += 4) {
        int   c0 = __ldg(&g_colS[i]),     c1 = __ldg(&g_colS[i + 1]);
        int   c2 = __ldg(&g_colS[i + 2]), c3 = __ldg(&g_colS[i + 3]);
        float w0 = __ldg(&g_wS[i]),       w1 = __ldg(&g_wS[i + 1]);
        float w2 = __ldg(&g_wS[i + 2]),   w3 = __ldg(&g_wS[i + 3]);
        uint2 r0 = __ldg(reinterpret_cast<const uint2*>(support + (size_t)c0 * NHID) + lane);
        uint2 r1 = __ldg(reinterpret_cast<const uint2*>(support + (size_t)c1 * NHID) + lane);
        uint2 r2 = __ldg(reinterpret_cast<const uint2*>(support + (size_t)c2 * NHID) + lane);
        uint2 r3 = __ldg(reinterpret_cast<const uint2*>(support + (size_t)c3 * NHID) + lane);
        float2 a0 = __half22float2(*reinterpret_cast<__half2*>(&r0.x));
        float2 b0 = __half22float2(*reinterpret_cast<__half2*>(&r0.y));
        float2 a1 = __half22float2(*reinterpret_cast<__half2*>(&r1.x));
        float2 b1 = __half22float2(*reinterpret_cast<__half2*>(&r1.y));
        float2 a2 = __half22float2(*reinterpret_cast<__half2*>(&r2.x));
        float2 b2 = __half22float2(*reinterpret_cast<__half2*>(&r2.y));
        float2 a3 = __half22float2(*reinterpret_cast<__half2*>(&r3.x));
        float2 b3 = __half22float2(*reinterpret_cast<__half2*>(&r3.y));
        acc.x = fmaf(w0, a0.x, acc.x); acc.y = fmaf(w0, a0.y, acc.y);
        acc.z = fmaf(w0, b0.x, acc.z); acc.w = fmaf(w0, b0.y, acc.w);
        acc.x = fmaf(w1, a1.x, acc.x); acc.y = fmaf(w1, a1.y, acc.y);
        acc.z = fmaf(w1, b1.x, acc.z); acc.w = fmaf(w1, b1.y, acc.w);
        acc.x = fmaf(w2, a2.x, acc.x); acc.y = fmaf(w2, a2.y, acc.y);
        acc.z = fmaf(w2, b2.x, acc.z); acc.w = fmaf(w2, b2.y, acc.w);
        acc.x = fmaf(w3, a3.x, acc.x); acc.y = fmaf(w3, a3.y, acc.y);
        acc.z = fmaf(w3, b3.x, acc.z); acc.w = fmaf(w3, b3.y, acc.w);
    }
    for (; i < e; i++) {
        int   c = __ldg(&g_colS[i]);
        float w = __ldg(&g_wS[i]);
        uint2 r = __ldg(reinterpret_cast<const uint2*>(support + (size_t)c * NHID) + lane);
        float2 a = __half22float2(*reinterpret_cast<__half2*>(&r.x));
        float2 b = __half22float2(*reinterpret_cast<__half2*>(&r.y));
        acc.x = fmaf(w, a.x, acc.x); acc.y = fmaf(w, a.y, acc.y);
        acc.z = fmaf(w, b.x, acc.z); acc.w = fmaf(w, b.y, acc.w);
    }
    float4 b = __ldg(reinterpret_cast<const float4*>(bias) + lane);
    acc.x = fmaxf(acc.x + b.x, 0.f);
    acc.y = fmaxf(acc.y + b.y, 0.f);
    acc.z = fmaxf(acc.z + b.z, 0.f);
    acc.w = fmaxf(acc.w + b.w, 0.f);
    __half2 p0 = __floats2half2_rn(acc.x, acc.y);
    __half2 p1 = __floats2half2_rn(acc.z, acc.w);
    uint2 st;
    st.x = *reinterpret_cast<uint32_t*>(&p0);
    st.y = *reinterpret_cast<uint32_t*>(&p1);
    *(reinterpret_cast<uint2*>(out + (size_t)warp * NHID) + lane) = st;
}

// ===========================================================================
extern "C" void kernel_launch(void* const* d_in, const int* in_sizes, int n_in,
                              void* d_out, int out_size)
{
    const float* x      = (const float*)d_in[0];
    const int*   ei     = (const int*)  d_in[1];
    const float* ew     = (const float*)d_in[2];
    const float* gc1_w  = (const float*)d_in[3];
    const float* gc1_b  = (const float*)d_in[4];
    const float* gc2_w  = (const float*)d_in[5];
    const float* gc2_b  = (const float*)d_in[6];
    const float* mu_w   = (const float*)d_in[7];
    const float* mu_b   = (const float*)d_in[8];
    const float* lv_w   = (const float*)d_in[9];
    const float* lv_b   = (const float*)d_in[10];
    float* out = (float*)d_out;

    __half *xh, *sup, *h, *w1t, *w2t, *wct;
    float *bcatf;
    int *cnt;
    cudaGetSymbolAddress((void**)&xh,   g_xh);
    cudaGetSymbolAddress((void**)&sup,  g_sup);
    cudaGetSymbolAddress((void**)&h,    g_h);
    cudaGetSymbolAddress((void**)&w1t,  g_w1t);
    cudaGetSymbolAddress((void**)&w2t,  g_w2t);
    cudaGetSymbolAddress((void**)&wct,  g_wct);
    cudaGetSymbolAddress((void**)&bcatf, g_bcatf);
    cudaGetSymbolAddress((void**)&cnt,  g_cnt);

    const int gemmBlocks = (NN + 127) / 128;                 // 782
    const int edgeBlocks = (EE + 255) / 256;
    const int spmmBlocks = (NN * 32 + 255) / 256;

    // ---- Prep: fp16 x, transposed fp16 weights ----
    convert_x<<<(int)(((size_t)NN * NFEAT / 8 + 255) / 256), 256>>>(x);
    prep_weights<<<(NHID * NFEAT + 255) / 256, 256>>>(gc1_w, gc2_w, mu_w, lv_w, mu_b, lv_b);

    // ---- CSR build (reused by both spmm layers) ----
    cudaMemsetAsync(cnt, 0, NN * sizeof(int));
    hist_kernel<<<edgeBlocks, 256>>>(ei);
    scan1_kernel<<<NSCANBLK, 256>>>();
    scan2_kernel<<<1, 32>>>();
    scan3_kernel<<<(NTOT + 255) / 256, 256>>>();
    cudaMemsetAsync(cnt, 0, NN * sizeof(int));
    scatter_kernel<<<edgeBlocks, 256>>>(ei, ew);

    // ---- Layer 1 ----
    mma_gemm<256, false><<<gemmBlocks, 256>>>(xh, w1t, nullptr, sup, NN);
    spmm_csr_bias_relu<<<spmmBlocks, 256>>>(sup, gc1_b, h);

    // ---- Layer 2 ----
    mma_gemm<128, false><<<gemmBlocks, 256>>>(h, w2t, nullptr, sup, NN);
    spmm_csr_bias_relu<<<spmmBlocks, 256>>>(sup, gc2_b, h);

    // ---- Fused heads ----
    mma_gemm<128, true><<<gemmBlocks, 256>>>(h, wct, bcatf, out, NN);
}

// round 10
// speedup vs baseline: 3.4502x; 1.0329x over previous
#include <cuda_runtime.h>
#include <cuda_fp16.h>
#include <cstdint>

// Problem constants
#define NN 100000
#define EE 1600000
#define NFEAT 256
#define NHID 128
#define LATENT 64
#define SCAN_CHUNK 2048
#define NTOT (NN + 1)
#define NSCANBLK ((NTOT + SCAN_CHUNK - 1) / SCAN_CHUNK)

// Scratch (allocation-free rule: __device__ globals)
__device__ __half g_sup[(size_t)NN * NHID];    // fp16 support (gemm out -> spmm in)
__device__ __half g_h[(size_t)NN * NHID];      // fp16 h1/h2 (spmm out -> gemm in)
__device__ __half g_w1t[NHID * NFEAT];         // W1^T [128,256] fp16
__device__ __half g_w2t[NHID * NHID];          // W2^T [128,128] fp16
__device__ __half g_wct[NHID * NHID];          // [mu|lv]^T [128,128] fp16
__device__ float  g_bcatf[NHID];
__device__ int    g_cnt[NN];
__device__ int    g_rowptr[NTOT];
__device__ int    g_blocksums[NSCANBLK + 1];
__device__ int    g_colS[EE];
__device__ float  g_wS[EE];

// ===========================================================================
// mma.sync helpers
// ===========================================================================
__device__ __forceinline__ uint32_t smem_to_u32(const void* p) {
    uint32_t a;
    asm("{ .reg .u64 t; cvta.to.shared.u64 t, %1; cvt.u32.u64 %0, t; }"
        : "=r"(a) : "l"(p));
    return a;
}

__device__ __forceinline__ void ldsm_x4(uint32_t& r0, uint32_t& r1,
                                        uint32_t& r2, uint32_t& r3, uint32_t addr)
{
    asm volatile("ldmatrix.sync.aligned.m8n8.x4.shared.b16 {%0,%1,%2,%3}, [%4];"
                 : "=r"(r0), "=r"(r1), "=r"(r2), "=r"(r3) : "r"(addr));
}

__device__ __forceinline__ void mma16816(float* c, const uint32_t* a, const uint32_t* b)
{
    asm volatile(
        "mma.sync.aligned.m16n8k16.row.col.f32.f16.f16.f32 "
        "{%0,%1,%2,%3}, {%4,%5,%6,%7}, {%8,%9}, {%0,%1,%2,%3};"
        : "+f"(c[0]), "+f"(c[1]), "+f"(c[2]), "+f"(c[3])
        : "r"(a[0]), "r"(a[1]), "r"(a[2]), "r"(a[3]), "r"(b[0]), "r"(b[1]));
}

// ===========================================================================
// HMMA GEMM: C[M,128] = A[M,KDIM] @ Bt[128,KDIM]^T, fp32 acc.
// AFP32: A is fp32 in gmem, converted to fp16 in the tile loader.
// HEADS=false -> fp16 store; HEADS=true -> fp32 +bias split mu/log_var.
// CTA: 256 thr = 8 warps (4 warpRow x 2 warpCol); warp tile 32x64.
// ===========================================================================
#define ROWP 24   // padded row stride in halves (48B): conflict-free ldmatrix

template <int KDIM, bool HEADS, bool AFP32>
__global__ __launch_bounds__(256) void mma_gemm(
    const void* __restrict__ Av, const __half* __restrict__ Bt,
    const float* __restrict__ bias, void* __restrict__ outv, int M)
{
    __shared__ __align__(16) __half sA[128 * ROWP];
    __shared__ __align__(16) __half sB[128 * ROWP];

    const int tid  = threadIdx.x;
    const int warp = tid >> 5, lane = tid & 31;
    const int warpM = (warp >> 1) * 32;      // 0,32,64,96
    const int warpN = (warp & 1) * 64;       // 0,64
    const int blockRow = blockIdx.x * 128;

    const uint32_t sAb = smem_to_u32(sA);
    const uint32_t sBb = smem_to_u32(sB);

    float acc[2][8][4];
#pragma unroll
    for (int i = 0; i < 2; i++)
#pragma unroll
        for (int j = 0; j < 8; j++)
#pragma unroll
            for (int k = 0; k < 4; k++) acc[i][j][k] = 0.f;

    // Stage loader indices: thread t -> row t/2, 8-half chunk t%2
    const int ldRow = tid >> 1;
    const int ldChunk = (tid & 1) * 8;
    const int gRowA = blockRow + ldRow;

    // A (x4): row = warpM + (lane&15), chunk = (lane>>4)*8
    const uint32_t aOffBase =
        (uint32_t)(warpM + (lane & 15)) * (ROWP * 2) + (uint32_t)((lane >> 4) * 16);
    // B (x4, non-trans; Bt[n][k] row-major = mma "col" operand)
    const uint32_t bOffBase =
        (uint32_t)(warpN + ((lane >> 4) << 3) + (lane & 7)) * (ROWP * 2)
        + (uint32_t)(((lane >> 3) & 1) * 16);

#pragma unroll 1
    for (int k0 = 0; k0 < KDIM; k0 += 16) {
        // Stage A tile (optionally converting fp32 -> fp16)
        uint4 va = make_uint4(0u, 0u, 0u, 0u);
        if (gRowA < M) {
            if (AFP32) {
                const float* A32 = (const float*)Av;
                float4 f0 = *reinterpret_cast<const float4*>(A32 + (size_t)gRowA * KDIM + k0 + ldChunk);
                float4 f1 = *reinterpret_cast<const float4*>(A32 + (size_t)gRowA * KDIM + k0 + ldChunk + 4);
                __half2 p0 = __floats2half2_rn(f0.x, f0.y);
                __half2 p1 = __floats2half2_rn(f0.z, f0.w);
                __half2 p2 = __floats2half2_rn(f1.x, f1.y);
                __half2 p3 = __floats2half2_rn(f1.z, f1.w);
                va.x = *reinterpret_cast<uint32_t*>(&p0);
                va.y = *reinterpret_cast<uint32_t*>(&p1);
                va.z = *reinterpret_cast<uint32_t*>(&p2);
                va.w = *reinterpret_cast<uint32_t*>(&p3);
            } else {
                const __half* A16 = (const __half*)Av;
                va = *reinterpret_cast<const uint4*>(A16 + (size_t)gRowA * KDIM + k0 + ldChunk);
            }
        }
        *reinterpret_cast<uint4*>(sA + ldRow * ROWP + ldChunk) = va;
        uint4 vb = *reinterpret_cast<const uint4*>(Bt + (size_t)ldRow * KDIM + k0 + ldChunk);
        *reinterpret_cast<uint4*>(sB + ldRow * ROWP + ldChunk) = vb;
        __syncthreads();

        uint32_t af[2][4];
#pragma unroll
        for (int mi = 0; mi < 2; mi++)
            ldsm_x4(af[mi][0], af[mi][1], af[mi][2], af[mi][3],
                    sAb + aOffBase + (uint32_t)mi * 16 * (ROWP * 2));

        uint32_t bf[8][2];
#pragma unroll
        for (int nj = 0; nj < 4; nj++) {
            uint32_t b0, b1, b2, b3;
            ldsm_x4(b0, b1, b2, b3,
                    sBb + bOffBase + (uint32_t)nj * 16 * (ROWP * 2));
            bf[nj * 2][0] = b0;     bf[nj * 2][1] = b1;
            bf[nj * 2 + 1][0] = b2; bf[nj * 2 + 1][1] = b3;
        }

#pragma unroll
        for (int mi = 0; mi < 2; mi++)
#pragma unroll
            for (int ni = 0; ni < 8; ni++)
                mma16816(acc[mi][ni], af[mi], bf[ni]);
        __syncthreads();
    }

    // Epilogue: c-frag layout (g=lane>>2, tg=lane&3)
    const int g = lane >> 2, tg = lane & 3;
#pragma unroll
    for (int mi = 0; mi < 2; mi++) {
        int r0 = blockRow + warpM + mi * 16 + g;      // rows r0 and r0+8
#pragma unroll
        for (int ni = 0; ni < 8; ni++) {
            int col = warpN + ni * 8 + tg * 2;
            if (HEADS) {
                float* out = reinterpret_cast<float*>(outv);
                size_t regionOff = (col < LATENT) ? 0 : (size_t)NN * LATENT;
                int c0 = col & (LATENT - 1);
                float bx = bias[col], by = bias[col + 1];
                if (r0 < M) {
                    float2 v = make_float2(acc[mi][ni][0] + bx, acc[mi][ni][1] + by);
                    *reinterpret_cast<float2*>(out + regionOff + (size_t)r0 * LATENT + c0) = v;
                }
                if (r0 + 8 < M) {
                    float2 v = make_float2(acc[mi][ni][2] + bx, acc[mi][ni][3] + by);
                    *reinterpret_cast<float2*>(out + regionOff + (size_t)(r0 + 8) * LATENT + c0) = v;
                }
            } else {
                __half* out = reinterpret_cast<__half*>(outv);
                if (r0 < M) {
                    __half2 h = __floats2half2_rn(acc[mi][ni][0], acc[mi][ni][1]);
                    *reinterpret_cast<__half2*>(out + (size_t)r0 * NHID + col) = h;
                }
                if (r0 + 8 < M) {
                    __half2 h = __floats2half2_rn(acc[mi][ni][2], acc[mi][ni][3]);
                    *reinterpret_cast<__half2*>(out + (size_t)(r0 + 8) * NHID + col) = h;
                }
            }
        }
    }
}

// ===========================================================================
// Prep: transposed fp16 weights + concatenated head bias
// ===========================================================================
__global__ __launch_bounds__(256) void prep_weights(
    const float* __restrict__ gc1_w, const float* __restrict__ gc2_w,
    const float* __restrict__ mu_w, const float* __restrict__ lv_w,
    const float* __restrict__ mu_b, const float* __restrict__ lv_b)
{
    int i = blockIdx.x * blockDim.x + threadIdx.x;
    if (i < NHID * NFEAT) {         // w1t[n,k] = gc1_w[k,n]
        int n = i / NFEAT, k = i % NFEAT;
        g_w1t[i] = __float2half_rn(gc1_w[k * NHID + n]);
    }
    if (i < NHID * NHID) {          // w2t / wct
        int n = i / NHID, k = i % NHID;
        g_w2t[i] = __float2half_rn(gc2_w[k * NHID + n]);
        g_wct[i] = __float2half_rn(n < LATENT ? mu_w[k * LATENT + n]
                                              : lv_w[k * LATENT + n - LATENT]);
    }
    if (i < NHID)
        g_bcatf[i] = (i < LATENT) ? mu_b[i] : lv_b[i - LATENT];
}

// ===========================================================================
// CSR build: histogram -> exclusive scan -> scatter
// ===========================================================================
__global__ __launch_bounds__(256) void hist_kernel(const int* __restrict__ ei)
{
    int e = blockIdx.x * blockDim.x + threadIdx.x;
    if (e < EE) atomicAdd(&g_cnt[ei[e]], 1);
}

__global__ __launch_bounds__(256) void scan1_kernel()
{
    __shared__ int sh[256];
    int b = blockIdx.x, t = threadIdx.x;
    int base = b * SCAN_CHUNK + t * 8;
    int v[8];
    int sum = 0;
#pragma unroll
    for (int k = 0; k < 8; k++) {
        int idx = base + k;
        int c = (idx < NN) ? g_cnt[idx] : 0;
        v[k] = sum;
        sum += c;
    }
    sh[t] = sum;
    __syncthreads();
    for (int off = 1; off < 256; off <<= 1) {
        int x = (t >= off) ? sh[t - off] : 0;
        __syncthreads();
        sh[t] += x;
        __syncthreads();
    }
    int threadExcl = sh[t] - sum;
#pragma unroll
    for (int k = 0; k < 8; k++) {
        int idx = base + k;
        if (idx < NTOT) g_rowptr[idx] = threadExcl + v[k];
    }
    if (t == 255) g_blocksums[b] = sh[255];
}

__global__ void scan2_kernel()
{
    if (threadIdx.x == 0) {
        int s = 0;
        for (int i = 0; i < NSCANBLK; i++) {
            int c = g_blocksums[i];
            g_blocksums[i] = s;
            s += c;
        }
    }
}

__global__ __launch_bounds__(256) void scan3_kernel()
{
    int i = blockIdx.x * blockDim.x + threadIdx.x;
    if (i < NTOT) g_rowptr[i] += g_blocksums[i / SCAN_CHUNK];
}

__global__ __launch_bounds__(256) void scatter_kernel(
    const int* __restrict__ ei, const float* __restrict__ ew)
{
    int e = blockIdx.x * blockDim.x + threadIdx.x;
    if (e >= EE) return;
    int r = ei[e];
    int pos = g_rowptr[r] + atomicAdd(&g_cnt[r], 1);
    g_colS[pos] = ei[EE + e];
    g_wS[pos]   = ew[e];
}

// ===========================================================================
// CSR SpMM v2: one warp per row; HALF-WARP per edge.
// Lanes 0-15 process even edges, lanes 16-31 odd edges; each lane holds
// 8 output columns (uint4 = 16B of fp16). One LDG.128 gathers TWO edges.
// Final shfl-down(16) reduction; lanes 0-15 apply bias+ReLU and store fp16.
// ===========================================================================
__global__ __launch_bounds__(256) void spmm_csr_bias_relu(
    const __half* __restrict__ support, const float* __restrict__ bias,
    __half* __restrict__ out)
{
    int row = (blockIdx.x * blockDim.x + threadIdx.x) >> 5;
    if (row >= NN) return;
    const int lane = threadIdx.x & 31;
    const int half = lane >> 4;           // 0: even edges, 1: odd edges
    const int sub  = lane & 15;           // 16B chunk within the 256B row

    const int s = __ldg(&g_rowptr[row]);
    const int e = __ldg(&g_rowptr[row + 1]);

    float acc[8];
#pragma unroll
    for (int j = 0; j < 8; j++) acc[j] = 0.f;

    int i = s;
    // 4 edges per iteration (2 per half-warp) for MLP
    for (; i + 4 <= e; i += 4) {
        int   c0 = __ldg(&g_colS[i + half]);
        int   c1 = __ldg(&g_colS[i + 2 + half]);
        float w0 = __ldg(&g_wS[i + half]);
        float w1 = __ldg(&g_wS[i + 2 + half]);
        uint4 v0 = __ldg(reinterpret_cast<const uint4*>(support + (size_t)c0 * NHID) + sub);
        uint4 v1 = __ldg(reinterpret_cast<const uint4*>(support + (size_t)c1 * NHID) + sub);
        const __half2* h0 = reinterpret_cast<const __half2*>(&v0);
        const __half2* h1 = reinterpret_cast<const __half2*>(&v1);
#pragma unroll
        for (int j = 0; j < 4; j++) {
            float2 f0 = __half22float2(h0[j]);
            float2 f1 = __half22float2(h1[j]);
            acc[2 * j + 0] = fmaf(w0, f0.x, acc[2 * j + 0]);
            acc[2 * j + 1] = fmaf(w0, f0.y, acc[2 * j + 1]);
            acc[2 * j + 0] = fmaf(w1, f1.x, acc[2 * j + 0]);
            acc[2 * j + 1] = fmaf(w1, f1.y, acc[2 * j + 1]);
        }
    }
    // 2 edges (1 per half-warp)
    for (; i + 2 <= e; i += 2) {
        int   c = __ldg(&g_colS[i + half]);
        float w = __ldg(&g_wS[i + half]);
        uint4 v = __ldg(reinterpret_cast<const uint4*>(support + (size_t)c * NHID) + sub);
        const __half2* h = reinterpret_cast<const __half2*>(&v);
#pragma unroll
        for (int j = 0; j < 4; j++) {
            float2 f = __half22float2(h[j]);
            acc[2 * j + 0] = fmaf(w, f.x, acc[2 * j + 0]);
            acc[2 * j + 1] = fmaf(w, f.y, acc[2 * j + 1]);
        }
    }
    // odd remainder: handled by lanes 0-15 only
    if (i < e && half == 0) {
        int   c = __ldg(&g_colS[i]);
        float w = __ldg(&g_wS[i]);
        uint4 v = __ldg(reinterpret_cast<const uint4*>(support + (size_t)c * NHID) + sub);
        const __half2* h = reinterpret_cast<const __half2*>(&v);
#pragma unroll
        for (int j = 0; j < 4; j++) {
            float2 f = __half22float2(h[j]);
            acc[2 * j + 0] = fmaf(w, f.x, acc[2 * j + 0]);
            acc[2 * j + 1] = fmaf(w, f.y, acc[2 * j + 1]);
        }
    }

    // Cross-half reduction: lane l += lane l+16
#pragma unroll
    for (int j = 0; j < 8; j++)
        acc[j] += __shfl_down_sync(0xFFFFFFFFu, acc[j], 16);

    if (half == 0) {
        float4 b0 = __ldg(reinterpret_cast<const float4*>(bias) + sub * 2);
        float4 b1 = __ldg(reinterpret_cast<const float4*>(bias) + sub * 2 + 1);
        float r0 = fmaxf(acc[0] + b0.x, 0.f), r1 = fmaxf(acc[1] + b0.y, 0.f);
        float r2 = fmaxf(acc[2] + b0.z, 0.f), r3 = fmaxf(acc[3] + b0.w, 0.f);
        float r4 = fmaxf(acc[4] + b1.x, 0.f), r5 = fmaxf(acc[5] + b1.y, 0.f);
        float r6 = fmaxf(acc[6] + b1.z, 0.f), r7 = fmaxf(acc[7] + b1.w, 0.f);
        __half2 p0 = __floats2half2_rn(r0, r1);
        __half2 p1 = __floats2half2_rn(r2, r3);
        __half2 p2 = __floats2half2_rn(r4, r5);
        __half2 p3 = __floats2half2_rn(r6, r7);
        uint4 st;
        st.x = *reinterpret_cast<uint32_t*>(&p0);
        st.y = *reinterpret_cast<uint32_t*>(&p1);
        st.z = *reinterpret_cast<uint32_t*>(&p2);
        st.w = *reinterpret_cast<uint32_t*>(&p3);
        *(reinterpret_cast<uint4*>(out + (size_t)row * NHID) + sub) = st;
    }
}

// ===========================================================================
extern "C" void kernel_launch(void* const* d_in, const int* in_sizes, int n_in,
                              void* d_out, int out_size)
{
    const float* x      = (const float*)d_in[0];
    const int*   ei     = (const int*)  d_in[1];
    const float* ew     = (const float*)d_in[2];
    const float* gc1_w  = (const float*)d_in[3];
    const float* gc1_b  = (const float*)d_in[4];
    const float* gc2_w  = (const float*)d_in[5];
    const float* gc2_b  = (const float*)d_in[6];
    const float* mu_w   = (const float*)d_in[7];
    const float* mu_b   = (const float*)d_in[8];
    const float* lv_w   = (const float*)d_in[9];
    const float* lv_b   = (const float*)d_in[10];
    float* out = (float*)d_out;

    __half *sup, *h, *w1t, *w2t, *wct;
    float *bcatf;
    int *cnt;
    cudaGetSymbolAddress((void**)&sup,  g_sup);
    cudaGetSymbolAddress((void**)&h,    g_h);
    cudaGetSymbolAddress((void**)&w1t,  g_w1t);
    cudaGetSymbolAddress((void**)&w2t,  g_w2t);
    cudaGetSymbolAddress((void**)&wct,  g_wct);
    cudaGetSymbolAddress((void**)&bcatf, g_bcatf);
    cudaGetSymbolAddress((void**)&cnt,  g_cnt);

    const int gemmBlocks = (NN + 127) / 128;                 // 782
    const int edgeBlocks = (EE + 255) / 256;
    const int spmmBlocks = (NN * 32 + 255) / 256;

    // ---- Prep: transposed fp16 weights (x converted inside gemm1) ----
    prep_weights<<<(NHID * NFEAT + 255) / 256, 256>>>(gc1_w, gc2_w, mu_w, lv_w, mu_b, lv_b);

    // ---- CSR build (reused by both spmm layers) ----
    cudaMemsetAsync(cnt, 0, NN * sizeof(int));
    hist_kernel<<<edgeBlocks, 256>>>(ei);
    scan1_kernel<<<NSCANBLK, 256>>>();
    scan2_kernel<<<1, 32>>>();
    scan3_kernel<<<(NTOT + 255) / 256, 256>>>();
    cudaMemsetAsync(cnt, 0, NN * sizeof(int));
    scatter_kernel<<<edgeBlocks, 256>>>(ei, ew);

    // ---- Layer 1 (A = fp32 x, converted in-loader) ----
    mma_gemm<256, false, true><<<gemmBlocks, 256>>>(x, w1t, nullptr, sup, NN);
    spmm_csr_bias_relu<<<spmmBlocks, 256>>>(sup, gc1_b, h);

    // ---- Layer 2 ----
    mma_gemm<128, false, false><<<gemmBlocks, 256>>>(h, w2t, nullptr, sup, NN);
    spmm_csr_bias_relu<<<spmmBlocks, 256>>>(sup, gc2_b, h);

    // ---- Fused heads ----
    mma_gemm<128, true, false><<<gemmBlocks, 256>>>(h, wct, bcatf, out, NN);
}